// round 1
// baseline (speedup 1.0000x reference)
#include <cuda_runtime.h>
#include <math.h>

#define NN 50000
#define NE 800000
#define E2 850000
#define NB 64

// ---------------- scratch (static device globals; no allocation) ----------------
__device__ float g_deg[NN];
__device__ float g_dinv[NN];
__device__ int   g_indeg[NN];
__device__ int   g_off[NN + 1];
__device__ int   g_cur[NN];
__device__ int   g_ssrc[E2];
__device__ float g_snorm[E2];
__device__ float g_h[NN * 36];      // GCN-transformed features, padded 33->36
__device__ float g_xpn[NN * 36];    // after GCN+relu+BN, padded
__device__ float g_xl[NN * 132];
__device__ float g_xr[NN * 132];
__device__ float g_xp2[NN * 132];   // GAT output
__device__ float g_ebuf[E2 * 2];
__device__ float g_pool[NB * 132];
__device__ float g_cnt[NB];
__device__ float g_W1t[3000 * 256];
__device__ float g_W2t[2998 * 256];
__device__ float g_acc1[NB * 5 * 256];
__device__ float g_acc2[NB * 65 * 256];
__device__ float g_y1[NB * 3872];
__device__ float g_y2[NB * 3872];
__device__ float g_hid[NB * 1024];

// ---------------- init ----------------
__global__ void k_init() {
    int i = blockIdx.x * blockDim.x + threadIdx.x;
    if (i < NN) { g_deg[i] = 1.0f; g_indeg[i] = 1; }   // self-loop contribution
    if (i < NB * 132) g_pool[i] = 0.0f;
    if (i < NB) g_cnt[i] = 0.0f;
}

// ---------------- degree / indegree over edges ----------------
__global__ void k_edge_count(const int* __restrict__ ei, const float* __restrict__ w) {
    int e = blockIdx.x * blockDim.x + threadIdx.x;
    if (e >= NE) return;
    int d = ei[NE + e];
    atomicAdd(&g_deg[d], w[e]);
    atomicAdd(&g_indeg[d], 1);
}

__global__ void k_dinv() {
    int i = blockIdx.x * blockDim.x + threadIdx.x;
    if (i < NN) g_dinv[i] = rsqrtf(g_deg[i]);
}

// ---------------- single-block scan of indeg -> offsets ----------------
__global__ void k_scan() {
    __shared__ int warpsum[32];
    __shared__ int s_carry;
    int lane = threadIdx.x & 31, wid = threadIdx.x >> 5;
    if (threadIdx.x == 0) s_carry = 0;
    __syncthreads();
    for (int base = 0; base < NN; base += 1024) {
        int i = base + threadIdx.x;
        int v = (i < NN) ? g_indeg[i] : 0;
        int x = v;
        #pragma unroll
        for (int off = 1; off < 32; off <<= 1) {
            int t = __shfl_up_sync(0xffffffffu, x, off);
            if (lane >= off) x += t;
        }
        if (lane == 31) warpsum[wid] = x;
        __syncthreads();
        if (wid == 0) {
            int s = warpsum[lane];
            #pragma unroll
            for (int off = 1; off < 32; off <<= 1) {
                int t = __shfl_up_sync(0xffffffffu, s, off);
                if (lane >= off) s += t;
            }
            warpsum[lane] = s;
        }
        __syncthreads();
        int wpre = (wid > 0) ? warpsum[wid - 1] : 0;
        int incl = x + wpre;
        int carry = s_carry;
        if (i < NN) g_off[i] = carry + incl - v;
        __syncthreads();
        if (threadIdx.x == 1023) s_carry = carry + incl;
        __syncthreads();
    }
    if (threadIdx.x == 0) g_off[NN] = s_carry;
}

__global__ void k_cursor() {
    int i = blockIdx.x * blockDim.x + threadIdx.x;
    if (i < NN) g_cur[i] = g_off[i];
}

// ---------------- counting-sort scatter (CSR by dst) ----------------
__global__ void k_scatter(const int* __restrict__ ei, const float* __restrict__ w) {
    int e = blockIdx.x * blockDim.x + threadIdx.x;
    if (e >= NE) return;
    int s = ei[e], d = ei[NE + e];
    int p = atomicAdd(&g_cur[d], 1);
    g_ssrc[p] = s;
    g_snorm[p] = g_dinv[s] * w[e] * g_dinv[d];
}

__global__ void k_selfloop() {
    int i = blockIdx.x * blockDim.x + threadIdx.x;
    if (i >= NN) return;
    int p = atomicAdd(&g_cur[i], 1);
    g_ssrc[p] = i;
    g_snorm[p] = g_dinv[i] * g_dinv[i];
}

// ---------------- GCN: h = pro_x @ gcn_w.T (padded to 36 cols) ----------------
__global__ void k_gcn_h(const float* __restrict__ x, const float* __restrict__ W) {
    __shared__ float Ws[33 * 33];
    __shared__ float xs[8][33];
    int tx = threadIdx.x, ty = threadIdx.y;
    int tid = ty * 36 + tx;
    for (int i = tid; i < 1089; i += 288) Ws[i] = W[i];
    int n = blockIdx.x * 8 + ty;
    if (n < NN && tx < 33) xs[ty][tx] = x[n * 33 + tx];
    __syncthreads();
    if (n >= NN) return;
    float a = 0.0f;
    if (tx < 33) {
        #pragma unroll
        for (int k = 0; k < 33; k++) a += xs[ty][k] * Ws[tx * 33 + k];
    }
    g_h[n * 36 + tx] = (tx < 33) ? a : 0.0f;
}

// ---------------- GCN aggregation (warp per dst) + relu + BN ----------------
__global__ void k_gcn_agg(const float* __restrict__ gcnb, const float* __restrict__ bm,
                          const float* __restrict__ bv, const float* __restrict__ bw,
                          const float* __restrict__ bb) {
    int d = blockIdx.x * 8 + (threadIdx.x >> 5);
    int lane = threadIdx.x & 31;
    if (d >= NN) return;
    int beg = g_off[d], end = g_off[d + 1];
    float a0 = 0.0f, a1 = 0.0f;
    for (int e = beg; e < end; e++) {
        int s = g_ssrc[e];
        float nm = g_snorm[e];
        a0 += g_h[s * 36 + lane] * nm;
        a1 += g_h[s * 36 + 32] * nm;   // channel 32 (broadcast load)
    }
    float c0 = fmaxf(a0 + gcnb[lane], 0.0f);
    float inv0 = bw[lane] * rsqrtf(bv[lane] + 1e-5f);
    g_xpn[d * 36 + lane] = c0 * inv0 + (bb[lane] - bm[lane] * inv0);
    if (lane == 0) {
        float c1 = fmaxf(a1 + gcnb[32], 0.0f);
        float inv1 = bw[32] * rsqrtf(bv[32] + 1e-5f);
        g_xpn[d * 36 + 32] = c1 * inv1 + (bb[32] - bm[32] * inv1);
        g_xpn[d * 36 + 33] = 0.0f;
        g_xpn[d * 36 + 34] = 0.0f;
        g_xpn[d * 36 + 35] = 0.0f;
    }
}

// ---------------- GAT projections: xl = xp @ wl.T, xr = xp @ wr.T ----------------
#define LR_NPB 64
__global__ void k_gat_lr(const float* __restrict__ wl, const float* __restrict__ wr) {
    __shared__ float Wsh[2 * 132 * 33];
    __shared__ float xs[33];
    int t = threadIdx.x;  // 0..263
    for (int i = t; i < 4356; i += 264) Wsh[i] = wl[i];
    for (int i = t; i < 4356; i += 264) Wsh[4356 + i] = wr[i];
    __syncthreads();
    int c = t % 132, side = t / 132;
    float wreg[33];
    #pragma unroll
    for (int k = 0; k < 33; k++) wreg[k] = Wsh[side * 4356 + c * 33 + k];
    float* outb = side ? g_xr : g_xl;
    int n0 = blockIdx.x * LR_NPB;
    int n1 = min(n0 + LR_NPB, NN);
    for (int n = n0; n < n1; n++) {
        __syncthreads();
        if (t < 33) xs[t] = g_xpn[n * 36 + t];
        __syncthreads();
        float a = 0.0f;
        #pragma unroll
        for (int k = 0; k < 33; k++) a += wreg[k] * xs[k];
        outb[n * 132 + c] = a;
    }
}

// ---------------- GATv2: warp per dst, fused two-pass softmax + aggregate ----------------
__global__ void k_gat(const float* __restrict__ att, const float* __restrict__ gb) {
    int d = blockIdx.x * 8 + (threadIdx.x >> 5);
    int lane = threadIdx.x & 31;
    if (d >= NN) return;
    float xrd[5], atv[5];
    #pragma unroll
    for (int j = 0; j < 5; j++) {
        int c = lane + 32 * j;
        bool ok = c < 132;
        xrd[j] = ok ? g_xr[d * 132 + c] : 0.0f;
        atv[j] = ok ? att[ok ? c : 0] : 0.0f;
    }
    int beg = g_off[d], end = g_off[d + 1];
    float m0 = -1e30f, m1 = -1e30f;
    for (int e = beg; e < end; e++) {
        int s = g_ssrc[e];
        float p0 = 0.0f, p1 = 0.0f;
        #pragma unroll
        for (int j = 0; j < 5; j++) {
            int c = lane + 32 * j;
            if (c < 132) {
                float v = g_xl[s * 132 + c] + xrd[j];
                v = v > 0.0f ? v : 0.2f * v;
                float tt = v * atv[j];
                if (c < 66) p0 += tt; else p1 += tt;
            }
        }
        #pragma unroll
        for (int o = 16; o; o >>= 1) {
            p0 += __shfl_xor_sync(0xffffffffu, p0, o);
            p1 += __shfl_xor_sync(0xffffffffu, p1, o);
        }
        if (lane == 0) { g_ebuf[2 * e] = p0; g_ebuf[2 * e + 1] = p1; }
        m0 = fmaxf(m0, p0); m1 = fmaxf(m1, p1);
    }
    float s0 = 0.0f, s1 = 0.0f;
    float acc[5] = {0.f, 0.f, 0.f, 0.f, 0.f};
    for (int e = beg; e < end; e++) {
        int s = g_ssrc[e];
        float a0 = __expf(g_ebuf[2 * e] - m0);
        float a1 = __expf(g_ebuf[2 * e + 1] - m1);
        s0 += a0; s1 += a1;
        #pragma unroll
        for (int j = 0; j < 5; j++) {
            int c = lane + 32 * j;
            if (c < 132) acc[j] += (c < 66 ? a0 : a1) * g_xl[s * 132 + c];
        }
    }
    #pragma unroll
    for (int j = 0; j < 5; j++) {
        int c = lane + 32 * j;
        if (c < 132) {
            float o = acc[j] / (c < 66 ? s0 : s1) + gb[c];
            g_xp2[d * 132 + c] = fmaxf(o, 0.0f);
        }
    }
}

// ---------------- mean pool (exploits sorted pro_batch) ----------------
__global__ void k_pool(const int* __restrict__ batch) {
    int c = threadIdx.x;  // 0..131
    int start = blockIdx.x * 782;
    int end = min(start + 782, NN);
    if (start >= end) return;
    int cur = batch[start];
    float sum = 0.0f, cnt = 0.0f;
    for (int n = start; n < end; n++) {
        int g = batch[n];
        if (g != cur) {
            atomicAdd(&g_pool[cur * 132 + c], sum);
            if (c == 0) atomicAdd(&g_cnt[cur], cnt);
            sum = 0.0f; cnt = 0.0f; cur = g;
        }
        sum += g_xp2[n * 132 + c];
        cnt += 1.0f;
    }
    atomicAdd(&g_pool[cur * 132 + c], sum);
    if (c == 0) atomicAdd(&g_cnt[cur], cnt);
}

// ---------------- protein MLP head ----------------
__global__ void k_fc1(const float* __restrict__ w, const float* __restrict__ b) {
    int g = blockIdx.x;
    __shared__ float m[132];
    if (threadIdx.x < 132) {
        float cnt = fmaxf(g_cnt[g], 1.0f);
        m[threadIdx.x] = g_pool[g * 132 + threadIdx.x] / cnt;
    }
    __syncthreads();
    int wid = threadIdx.x >> 5, lane = threadIdx.x & 31;
    for (int o = wid; o < 1024; o += 8) {
        float acc = 0.0f;
        for (int k = lane; k < 132; k += 32) acc += w[o * 132 + k] * m[k];
        #pragma unroll
        for (int off = 16; off; off >>= 1) acc += __shfl_xor_sync(0xffffffffu, acc, off);
        if (lane == 0) g_hid[g * 1024 + o] = fmaxf(acc + b[o], 0.0f);
    }
}

__global__ void k_fc2(const float* __restrict__ w, const float* __restrict__ b, float* __restrict__ out) {
    int g = blockIdx.x;
    int wid = threadIdx.x >> 5, lane = threadIdx.x & 31;
    for (int o = wid; o < 128; o += 8) {
        float acc = 0.0f;
        for (int k = lane; k < 1024; k += 32) acc += w[o * 1024 + k] * g_hid[g * 1024 + k];
        #pragma unroll
        for (int off = 16; off; off >>= 1) acc += __shfl_xor_sync(0xffffffffu, acc, off);
        if (lane == 0) out[8192 + g * 128 + o] = acc + b[o];
    }
}

// ---------------- RNA branch ----------------
// transpose conv weights [O=32][C][K=8] -> [C][O*8]
__global__ void k_transpose(const float* __restrict__ w, int C, int which) {
    float* wt = which ? g_W2t : g_W1t;
    int t = blockIdx.x * blockDim.x + threadIdx.x;
    if (t >= C * 256) return;
    int c = t >> 8, j = t & 255, o = j >> 3, k = j & 7;
    wt[t] = w[o * C * 8 + c * 8 + k];
}

// acc[b][v][j] = sum over positions with token v of wt[c][j]
__global__ void k_rna_acc(const int* __restrict__ rna, int C, int V, int which) {
    extern __shared__ float ash[];  // V * blockDim.x
    const float* wt = which ? g_W2t : g_W1t;
    float* acc = which ? g_acc2 : g_acc1;
    int b = blockIdx.x;
    int JW = blockDim.x;
    int joff = blockIdx.y * JW;
    int j = threadIdx.x;
    for (int v = 0; v < V; v++) ash[v * JW + j] = 0.0f;
    __syncthreads();
    const int* row = rna + b * C;
    for (int c = 0; c < C; c++) {
        int v = __ldg(&row[c]);
        ash[v * JW + j] += wt[c * 256 + joff + j];
    }
    for (int v = 0; v < V; v++) acc[b * V * 256 + v * 256 + joff + j] = ash[v * JW + j];
}

// y[b][o][l] = bias[o] + sum_v sum_k acc[b][v][o*8+k] * emb[v][l+k]
__global__ void k_conv(const float* __restrict__ emb, const float* __restrict__ bias, int V, int which) {
    extern __shared__ float sh[];
    const float* acc = which ? g_acc2 : g_acc1;
    float* y = which ? g_y2 : g_y1;
    float* emb_sh = sh;
    float* acc_sh = sh + V * 128;
    int b = blockIdx.x, o = blockIdx.y, t = threadIdx.x;
    for (int i = t; i < V * 128; i += 128) emb_sh[i] = emb[i];
    for (int i = t; i < V * 8; i += 128) {
        int v = i >> 3, k = i & 7;
        acc_sh[i] = acc[b * V * 256 + v * 256 + o * 8 + k];
    }
    __syncthreads();
    if (t < 121) {
        float s = bias[o];
        for (int v = 0; v < V; v++) {
            #pragma unroll
            for (int k = 0; k < 8; k++) s += acc_sh[v * 8 + k] * emb_sh[v * 128 + t + k];
        }
        y[b * 3872 + o * 121 + t] = s;
    }
}

// xc_rna[b][d] = sum_i fcw[d][i] * 0.5*(y1+y2)[b][i] + fcb[d]
__global__ void k_fc_rna(const float* __restrict__ w, const float* __restrict__ bias, float* __restrict__ out) {
    __shared__ float ys[3872];
    int b = blockIdx.x;
    for (int i = threadIdx.x; i < 3872; i += 256)
        ys[i] = 0.5f * (g_y1[b * 3872 + i] + g_y2[b * 3872 + i]);
    __syncthreads();
    int wid = threadIdx.x >> 5, lane = threadIdx.x & 31;
    for (int dcol = wid; dcol < 128; dcol += 8) {
        float acc = 0.0f;
        for (int i = lane; i < 3872; i += 32) acc += w[dcol * 3872 + i] * ys[i];
        #pragma unroll
        for (int off = 16; off; off >>= 1) acc += __shfl_xor_sync(0xffffffffu, acc, off);
        if (lane == 0) out[b * 128 + dcol] = acc + bias[dcol];
    }
}

// ---------------- launch ----------------
extern "C" void kernel_launch(void* const* d_in, const int* in_sizes, int n_in,
                              void* d_out, int out_size) {
    const int*   global_rna = (const int*)d_in[0];
    const int*   local_rna  = (const int*)d_in[1];
    const float* pro_x      = (const float*)d_in[2];
    const int*   ei         = (const int*)d_in[3];
    const float* pw         = (const float*)d_in[4];
    const int*   pb         = (const int*)d_in[5];
    const float* emb1       = (const float*)d_in[6];
    const float* emb2       = (const float*)d_in[7];
    const float* c1w        = (const float*)d_in[8];
    const float* c1b        = (const float*)d_in[9];
    const float* c2w        = (const float*)d_in[10];
    const float* c2b        = (const float*)d_in[11];
    const float* fxw        = (const float*)d_in[12];
    const float* fxb        = (const float*)d_in[13];
    const float* gcnw       = (const float*)d_in[14];
    const float* gcnb       = (const float*)d_in[15];
    const float* bnm        = (const float*)d_in[16];
    const float* bnv        = (const float*)d_in[17];
    const float* bnw        = (const float*)d_in[18];
    const float* bnb        = (const float*)d_in[19];
    const float* gwl        = (const float*)d_in[20];
    const float* gwr        = (const float*)d_in[21];
    const float* gatt       = (const float*)d_in[22];
    const float* gb         = (const float*)d_in[23];
    const float* f1w        = (const float*)d_in[24];
    const float* f1b        = (const float*)d_in[25];
    const float* f2w        = (const float*)d_in[26];
    const float* f2b        = (const float*)d_in[27];
    float* out = (float*)d_out;

    // ---- protein branch ----
    k_init<<<196, 256>>>();
    k_edge_count<<<3125, 256>>>(ei, pw);
    k_dinv<<<196, 256>>>();
    k_scan<<<1, 1024>>>();
    k_cursor<<<196, 256>>>();
    k_scatter<<<3125, 256>>>(ei, pw);
    k_selfloop<<<196, 256>>>();
    k_gcn_h<<<6250, dim3(36, 8)>>>(pro_x, gcnw);
    k_gcn_agg<<<6250, 256>>>(gcnb, bnm, bnv, bnw, bnb);
    k_gat_lr<<<(NN + LR_NPB - 1) / LR_NPB, 264>>>(gwl, gwr);
    k_gat<<<6250, 256>>>(gatt, gb);
    k_pool<<<64, 132>>>(pb);
    k_fc1<<<64, 256>>>(f1w, f1b);
    k_fc2<<<64, 256>>>(f2w, f2b, out);

    // ---- RNA branch ----
    k_transpose<<<3000, 256>>>(c1w, 3000, 0);
    k_transpose<<<2998, 256>>>(c2w, 2998, 1);
    k_rna_acc<<<dim3(64, 1), 256, 5 * 256 * 4>>>(global_rna, 3000, 5, 0);
    k_rna_acc<<<dim3(64, 2), 128, 65 * 128 * 4>>>(local_rna, 2998, 65, 1);
    k_conv<<<dim3(64, 32), 128, (5 * 128 + 5 * 8) * 4>>>(emb1, c1b, 5, 0);
    k_conv<<<dim3(64, 32), 128, (65 * 128 + 65 * 8) * 4>>>(emb2, c2b, 65, 1);
    k_fc_rna<<<64, 256>>>(fxw, fxb, out);
}

// round 5
// speedup vs baseline: 1.4753x; 1.4753x over previous
#include <cuda_runtime.h>
#include <math.h>

#define NN 50000
#define NE 800000
#define E2 850000
#define NB 64
#define SCAN_NBLK 98   // ceil(50000/512)

// ---------------- scratch ----------------
__device__ float g_deg[NN];
__device__ float g_dinv[NN];
__device__ int   g_indeg[NN];
__device__ int   g_off[NN + 1];
__device__ int   g_bsum[128];
__device__ int   g_cur[NN];
__device__ int   g_ssrc[E2];
__device__ float g_snorm[E2];
__device__ float g_h[NN * 36];
__device__ float g_xpn[NN * 36];
__device__ float g_xl[NN * 132];
__device__ float g_xr[NN * 132];
__device__ float g_xp2[NN * 132];
__device__ float g_pool[NB * 132];
__device__ float g_cnt[NB];
__device__ float g_W1t[3000 * 256];
__device__ float g_W2t[2998 * 256];
__device__ float g_acc1[NB * 5 * 256];
__device__ float g_acc2[NB * 65 * 256];
__device__ float g_y1[NB * 3872];
__device__ float g_y2[NB * 3872];
__device__ float g_hid[NB * 1024];

// ---------------- init (protein) ----------------
__global__ void k_init() {
    int i = blockIdx.x * blockDim.x + threadIdx.x;
    if (i < NN) { g_deg[i] = 1.0f; g_indeg[i] = 1; }
    if (i < NB * 132) g_pool[i] = 0.0f;
    if (i < NB) g_cnt[i] = 0.0f;
}

__global__ void k_edge_count(const int* __restrict__ ei, const float* __restrict__ w) {
    int e = blockIdx.x * blockDim.x + threadIdx.x;
    if (e >= NE) return;
    int d = ei[NE + e];
    atomicAdd(&g_deg[d], w[e]);
    atomicAdd(&g_indeg[d], 1);
}

__global__ void k_dinv() {
    int i = blockIdx.x * blockDim.x + threadIdx.x;
    if (i < NN) g_dinv[i] = rsqrtf(g_deg[i]);
}

// ---------------- multi-block scan ----------------
__global__ void k_scanA() {
    __shared__ int wsum[16];
    int i = blockIdx.x * 512 + threadIdx.x;
    int lane = threadIdx.x & 31, wid = threadIdx.x >> 5;
    int v = (i < NN) ? g_indeg[i] : 0;
    int x = v;
    #pragma unroll
    for (int off = 1; off < 32; off <<= 1) {
        int t = __shfl_up_sync(0xffffffffu, x, off);
        if (lane >= off) x += t;
    }
    if (lane == 31) wsum[wid] = x;
    __syncthreads();
    if (wid == 0) {
        int s = (lane < 16) ? wsum[lane] : 0;
        #pragma unroll
        for (int off = 1; off < 32; off <<= 1) {
            int t = __shfl_up_sync(0xffffffffu, s, off);
            if (lane >= off) s += t;
        }
        if (lane < 16) wsum[lane] = s;
    }
    __syncthreads();
    int pre = (wid > 0) ? wsum[wid - 1] : 0;
    int incl = x + pre;
    if (i < NN) g_off[i] = incl - v;           // block-local exclusive
    if (threadIdx.x == 511) g_bsum[blockIdx.x] = incl;  // block total
}

__global__ void k_scanB() {
    __shared__ int wtot[4];
    int t = threadIdx.x;        // 128 threads
    int lane = t & 31, wid = t >> 5;
    int v = (t < SCAN_NBLK) ? g_bsum[t] : 0;
    int x = v;
    #pragma unroll
    for (int off = 1; off < 32; off <<= 1) {
        int tt = __shfl_up_sync(0xffffffffu, x, off);
        if (lane >= off) x += tt;
    }
    if (lane == 31) wtot[wid] = x;
    __syncthreads();
    if (t == 0) {
        int run = 0;
        for (int k = 0; k < 4; k++) { int tmp = wtot[k]; wtot[k] = run; run += tmp; }
        g_off[NN] = run;
    }
    __syncthreads();
    int excl = x - v + wtot[wid];
    if (t < SCAN_NBLK) g_bsum[t] = excl;
}

__global__ void k_scanC() {
    int i = blockIdx.x * blockDim.x + threadIdx.x;
    if (i >= NN) return;
    int val = g_off[i] + g_bsum[i >> 9];
    g_off[i] = val;
    g_cur[i] = val;
}

// ---------------- counting-sort scatter ----------------
__global__ void k_scatter(const int* __restrict__ ei, const float* __restrict__ w) {
    int e = blockIdx.x * blockDim.x + threadIdx.x;
    if (e >= NE) return;
    int s = ei[e], d = ei[NE + e];
    int p = atomicAdd(&g_cur[d], 1);
    g_ssrc[p] = s;
    g_snorm[p] = g_dinv[s] * w[e] * g_dinv[d];
}

__global__ void k_selfloop() {
    int i = blockIdx.x * blockDim.x + threadIdx.x;
    if (i >= NN) return;
    int p = atomicAdd(&g_cur[i], 1);
    g_ssrc[p] = i;
    g_snorm[p] = g_dinv[i] * g_dinv[i];
}

// ---------------- GCN transform ----------------
__global__ void k_gcn_h(const float* __restrict__ x, const float* __restrict__ W) {
    __shared__ float Ws[33 * 33];
    __shared__ float xs[8][33];
    int tx = threadIdx.x, ty = threadIdx.y;
    int tid = ty * 36 + tx;
    for (int i = tid; i < 1089; i += 288) Ws[i] = W[i];
    int n = blockIdx.x * 8 + ty;
    if (n < NN && tx < 33) xs[ty][tx] = x[n * 33 + tx];
    __syncthreads();
    if (n >= NN) return;
    float a = 0.0f;
    if (tx < 33) {
        #pragma unroll
        for (int k = 0; k < 33; k++) a += xs[ty][k] * Ws[tx * 33 + k];
    }
    g_h[n * 36 + tx] = (tx < 33) ? a : 0.0f;
}

// ---------------- GCN aggregation + relu + BN ----------------
__global__ void k_gcn_agg(const float* __restrict__ gcnb, const float* __restrict__ bm,
                          const float* __restrict__ bv, const float* __restrict__ bw,
                          const float* __restrict__ bb) {
    int d = blockIdx.x * 8 + (threadIdx.x >> 5);
    int lane = threadIdx.x & 31;
    if (d >= NN) return;
    int beg = g_off[d], end = g_off[d + 1];
    float a0 = 0.0f, a1 = 0.0f;
    for (int e = beg; e < end; e++) {
        int s = g_ssrc[e];
        float nm = g_snorm[e];
        a0 += g_h[s * 36 + lane] * nm;
        a1 += g_h[s * 36 + 32] * nm;
    }
    float c0 = fmaxf(a0 + gcnb[lane], 0.0f);
    float inv0 = bw[lane] * rsqrtf(bv[lane] + 1e-5f);
    g_xpn[d * 36 + lane] = c0 * inv0 + (bb[lane] - bm[lane] * inv0);
    if (lane == 0) {
        float c1 = fmaxf(a1 + gcnb[32], 0.0f);
        float inv1 = bw[32] * rsqrtf(bv[32] + 1e-5f);
        g_xpn[d * 36 + 32] = c1 * inv1 + (bb[32] - bm[32] * inv1);
        g_xpn[d * 36 + 33] = 0.0f;
        g_xpn[d * 36 + 34] = 0.0f;
        g_xpn[d * 36 + 35] = 0.0f;
    }
}

// ---------------- GAT projections ----------------
#define LR_NPB 64
__global__ void k_gat_lr(const float* __restrict__ wl, const float* __restrict__ wr) {
    __shared__ float Wsh[2 * 132 * 33];
    __shared__ float xs[8][33];
    int t = threadIdx.x;  // 0..263
    for (int i = t; i < 4356; i += 264) Wsh[i] = wl[i];
    for (int i = t; i < 4356; i += 264) Wsh[4356 + i] = wr[i];
    __syncthreads();
    int c = t % 132, side = t / 132;
    float wreg[33];
    #pragma unroll
    for (int k = 0; k < 33; k++) wreg[k] = Wsh[side * 4356 + c * 33 + k];
    float* outb = side ? g_xr : g_xl;
    int n0 = blockIdx.x * LR_NPB;
    int n1 = min(n0 + LR_NPB, NN);
    for (int nb = n0; nb < n1; nb += 8) {
        __syncthreads();
        {   // 264 threads load 8 nodes x 33 feats
            int u = t / 33, k = t % 33;
            int n = nb + u;
            xs[u][k] = (n < NN) ? g_xpn[n * 36 + k] : 0.0f;
        }
        __syncthreads();
        #pragma unroll
        for (int u = 0; u < 8; u++) {
            int n = nb + u;
            if (n < n1) {
                float a = 0.0f;
                #pragma unroll
                for (int k = 0; k < 33; k++) a += wreg[k] * xs[u][k];
                outb[n * 132 + c] = a;
            }
        }
    }
}

// ---------------- GATv2: single-pass online softmax, float4 ----------------
__global__ void k_gat(const float* __restrict__ att, const float* __restrict__ gb) {
    int d = blockIdx.x * 8 + (threadIdx.x >> 5);
    int lane = threadIdx.x & 31;
    if (d >= NN) return;
    const float4* xr4 = (const float4*)(g_xr + d * 132);
    const float4* att4 = (const float4*)att;
    const float4* gb4 = (const float4*)gb;
    float4 z = make_float4(0.f, 0.f, 0.f, 0.f);
    float4 xr0 = xr4[lane];
    float4 at0 = att4[lane];
    float4 xr1 = (lane == 0) ? xr4[32] : z;
    float4 at1 = (lane == 0) ? att4[32] : z;
    int cb = 4 * lane;
    int beg = g_off[d], end = g_off[d + 1];
    float m0 = -1e30f, m1 = -1e30f, s0 = 0.f, s1 = 0.f;
    float4 acc0 = z, acc1 = z;
    for (int e = beg; e < end; e++) {
        int s = g_ssrc[e];
        const float4* xl4 = (const float4*)(g_xl + s * 132);
        float4 a0 = xl4[lane];
        float4 a1 = (lane == 0) ? xl4[32] : z;
        float p0 = 0.f, p1 = 0.f;
        {
            float v, tt;
            v = a0.x + xr0.x; v = v > 0.f ? v : 0.2f * v; tt = v * at0.x; if (cb + 0 < 66) p0 += tt; else p1 += tt;
            v = a0.y + xr0.y; v = v > 0.f ? v : 0.2f * v; tt = v * at0.y; if (cb + 1 < 66) p0 += tt; else p1 += tt;
            v = a0.z + xr0.z; v = v > 0.f ? v : 0.2f * v; tt = v * at0.z; if (cb + 2 < 66) p0 += tt; else p1 += tt;
            v = a0.w + xr0.w; v = v > 0.f ? v : 0.2f * v; tt = v * at0.w; if (cb + 3 < 66) p0 += tt; else p1 += tt;
            // channels 128..131 (head 1), nonzero only on lane 0
            v = a1.x + xr1.x; v = v > 0.f ? v : 0.2f * v; p1 += v * at1.x;
            v = a1.y + xr1.y; v = v > 0.f ? v : 0.2f * v; p1 += v * at1.y;
            v = a1.z + xr1.z; v = v > 0.f ? v : 0.2f * v; p1 += v * at1.z;
            v = a1.w + xr1.w; v = v > 0.f ? v : 0.2f * v; p1 += v * at1.w;
        }
        #pragma unroll
        for (int o = 16; o; o >>= 1) {
            p0 += __shfl_xor_sync(0xffffffffu, p0, o);
            p1 += __shfl_xor_sync(0xffffffffu, p1, o);
        }
        float n0 = fmaxf(m0, p0), n1 = fmaxf(m1, p1);
        float f0 = __expf(m0 - n0), w0 = __expf(p0 - n0);
        float f1 = __expf(m1 - n1), w1 = __expf(p1 - n1);
        s0 = s0 * f0 + w0; m0 = n0;
        s1 = s1 * f1 + w1; m1 = n1;
        float F0 = (cb + 0 < 66) ? f0 : f1, W0 = (cb + 0 < 66) ? w0 : w1;
        float F1 = (cb + 1 < 66) ? f0 : f1, W1 = (cb + 1 < 66) ? w0 : w1;
        float F2 = (cb + 2 < 66) ? f0 : f1, W2 = (cb + 2 < 66) ? w0 : w1;
        float F3 = (cb + 3 < 66) ? f0 : f1, W3 = (cb + 3 < 66) ? w0 : w1;
        acc0.x = acc0.x * F0 + W0 * a0.x;
        acc0.y = acc0.y * F1 + W1 * a0.y;
        acc0.z = acc0.z * F2 + W2 * a0.z;
        acc0.w = acc0.w * F3 + W3 * a0.w;
        acc1.x = acc1.x * f1 + w1 * a1.x;
        acc1.y = acc1.y * f1 + w1 * a1.y;
        acc1.z = acc1.z * f1 + w1 * a1.z;
        acc1.w = acc1.w * f1 + w1 * a1.w;
    }
    float4 gv = gb4[lane];
    float4 o;
    o.x = fmaxf(acc0.x / ((cb + 0 < 66) ? s0 : s1) + gv.x, 0.f);
    o.y = fmaxf(acc0.y / ((cb + 1 < 66) ? s0 : s1) + gv.y, 0.f);
    o.z = fmaxf(acc0.z / ((cb + 2 < 66) ? s0 : s1) + gv.z, 0.f);
    o.w = fmaxf(acc0.w / ((cb + 3 < 66) ? s0 : s1) + gv.w, 0.f);
    ((float4*)(g_xp2 + d * 132))[lane] = o;
    if (lane == 0) {
        float4 gv1 = gb4[32];
        float4 o1;
        o1.x = fmaxf(acc1.x / s1 + gv1.x, 0.f);
        o1.y = fmaxf(acc1.y / s1 + gv1.y, 0.f);
        o1.z = fmaxf(acc1.z / s1 + gv1.z, 0.f);
        o1.w = fmaxf(acc1.w / s1 + gv1.w, 0.f);
        ((float4*)(g_xp2 + d * 132))[32] = o1;
    }
}

// ---------------- mean pool ----------------
__global__ void k_pool(const int* __restrict__ batch) {
    int c = threadIdx.x;  // 0..131
    int start = blockIdx.x * 782;
    int end = min(start + 782, NN);
    if (start >= end) return;
    int cur = batch[start];
    float sum = 0.0f, cnt = 0.0f;
    for (int n = start; n < end; n++) {
        int g = batch[n];
        if (g != cur) {
            atomicAdd(&g_pool[cur * 132 + c], sum);
            if (c == 0) atomicAdd(&g_cnt[cur], cnt);
            sum = 0.0f; cnt = 0.0f; cur = g;
        }
        sum += g_xp2[n * 132 + c];
        cnt += 1.0f;
    }
    atomicAdd(&g_pool[cur * 132 + c], sum);
    if (c == 0) atomicAdd(&g_cnt[cur], cnt);
}

// ---------------- protein MLP head ----------------
__global__ void k_fc1(const float* __restrict__ w, const float* __restrict__ b) {
    int g = blockIdx.x;
    __shared__ float m[132];
    if (threadIdx.x < 132) {
        float cnt = fmaxf(g_cnt[g], 1.0f);
        m[threadIdx.x] = g_pool[g * 132 + threadIdx.x] / cnt;
    }
    __syncthreads();
    int wid = threadIdx.x >> 5, lane = threadIdx.x & 31;
    for (int o = wid; o < 1024; o += 8) {
        float acc = 0.0f;
        for (int k = lane; k < 132; k += 32) acc += w[o * 132 + k] * m[k];
        #pragma unroll
        for (int off = 16; off; off >>= 1) acc += __shfl_xor_sync(0xffffffffu, acc, off);
        if (lane == 0) g_hid[g * 1024 + o] = fmaxf(acc + b[o], 0.0f);
    }
}

__global__ void k_fc2(const float* __restrict__ w, const float* __restrict__ b, float* __restrict__ out) {
    int g = blockIdx.x;
    int wid = threadIdx.x >> 5, lane = threadIdx.x & 31;
    for (int o = wid; o < 128; o += 8) {
        float acc = 0.0f;
        for (int k = lane; k < 1024; k += 32) acc += w[o * 1024 + k] * g_hid[g * 1024 + k];
        #pragma unroll
        for (int off = 16; off; off >>= 1) acc += __shfl_xor_sync(0xffffffffu, acc, off);
        if (lane == 0) out[8192 + g * 128 + o] = acc + b[o];
    }
}

// ---------------- RNA branch ----------------
__global__ void k_transpose(const float* __restrict__ w, int C, int which) {
    float* wt = which ? g_W2t : g_W1t;
    int t = blockIdx.x * blockDim.x + threadIdx.x;
    if (t >= C * 256) return;
    int c = t >> 8, j = t & 255, o = j >> 3, k = j & 7;
    wt[t] = w[o * C * 8 + c * 8 + k];
}

// V=5: register accumulators, chunked over positions
__global__ void k_acc5(const int* __restrict__ rna) {
    int b = blockIdx.x;
    int c0 = blockIdx.y * 250;
    int j = threadIdx.x;  // 0..255
    const int* row = rna + b * 3000 + c0;
    const float* wt = g_W1t + (size_t)c0 * 256 + j;
    float a[5] = {0.f, 0.f, 0.f, 0.f, 0.f};
    #pragma unroll 10
    for (int c = 0; c < 250; c++) {
        int v = __ldg(&row[c]);
        float w = wt[c * 256];
        #pragma unroll
        for (int u = 0; u < 5; u++) a[u] += (v == u) ? w : 0.0f;
    }
    #pragma unroll
    for (int u = 0; u < 5; u++)
        atomicAdd(&g_acc1[b * 1280 + u * 256 + j], a[u]);
}

// V=65: shared accumulators, chunked, batched prefetch
__global__ void k_acc65(const int* __restrict__ rna) {
    __shared__ float ash[65 * 128];
    int b = blockIdx.x;
    int joff = blockIdx.y * 128;
    int ch = blockIdx.z;
    int j = threadIdx.x;  // 0..127
    int c0 = ch * 750, c1 = min(c0 + 750, 2998);
    #pragma unroll
    for (int v = 0; v < 65; v++) ash[v * 128 + j] = 0.0f;
    __syncthreads();
    const int* row = rna + b * 2998;
    const float* wt = g_W2t + joff + j;
    int c = c0;
    for (; c + 8 <= c1; c += 8) {
        int vs[8]; float ws[8];
        #pragma unroll
        for (int u = 0; u < 8; u++) vs[u] = __ldg(&row[c + u]);
        #pragma unroll
        for (int u = 0; u < 8; u++) ws[u] = wt[(size_t)(c + u) * 256];
        #pragma unroll
        for (int u = 0; u < 8; u++) ash[vs[u] * 128 + j] += ws[u];
    }
    for (; c < c1; c++) {
        int v = __ldg(&row[c]);
        ash[v * 128 + j] += wt[(size_t)c * 256];
    }
    __syncthreads();
    for (int v = 0; v < 65; v++)
        atomicAdd(&g_acc2[b * 16640 + v * 256 + joff + j], ash[v * 128 + j]);
}

__global__ void k_conv(const float* __restrict__ emb, const float* __restrict__ bias, int V, int which) {
    extern __shared__ float sh[];
    const float* acc = which ? g_acc2 : g_acc1;
    float* y = which ? g_y2 : g_y1;
    float* emb_sh = sh;
    float* acc_sh = sh + V * 128;
    int b = blockIdx.x, o = blockIdx.y, t = threadIdx.x;
    for (int i = t; i < V * 128; i += 128) emb_sh[i] = emb[i];
    for (int i = t; i < V * 8; i += 128) {
        int v = i >> 3, k = i & 7;
        acc_sh[i] = acc[b * V * 256 + v * 256 + o * 8 + k];
    }
    __syncthreads();
    if (t < 121) {
        float s = bias[o];
        for (int v = 0; v < V; v++) {
            #pragma unroll
            for (int k = 0; k < 8; k++) s += acc_sh[v * 8 + k] * emb_sh[v * 128 + t + k];
        }
        y[b * 3872 + o * 121 + t] = s;
    }
}

__global__ void k_fc_rna(const float* __restrict__ w, const float* __restrict__ bias, float* __restrict__ out) {
    __shared__ float ys[3872];
    int b = blockIdx.x;
    for (int i = threadIdx.x; i < 3872; i += 256)
        ys[i] = 0.5f * (g_y1[b * 3872 + i] + g_y2[b * 3872 + i]);
    __syncthreads();
    int wid = threadIdx.x >> 5, lane = threadIdx.x & 31;
    for (int dcol = wid; dcol < 128; dcol += 8) {
        float acc = 0.0f;
        for (int i = lane; i < 3872; i += 32) acc += w[dcol * 3872 + i] * ys[i];
        #pragma unroll
        for (int off = 16; off; off >>= 1) acc += __shfl_xor_sync(0xffffffffu, acc, off);
        if (lane == 0) out[b * 128 + dcol] = acc + bias[dcol];
    }
}

// ---------------- launch ----------------
extern "C" void kernel_launch(void* const* d_in, const int* in_sizes, int n_in,
                              void* d_out, int out_size) {
    const int*   global_rna = (const int*)d_in[0];
    const int*   local_rna  = (const int*)d_in[1];
    const float* pro_x      = (const float*)d_in[2];
    const int*   ei         = (const int*)d_in[3];
    const float* pw         = (const float*)d_in[4];
    const int*   pb         = (const int*)d_in[5];
    const float* emb1       = (const float*)d_in[6];
    const float* emb2       = (const float*)d_in[7];
    const float* c1w        = (const float*)d_in[8];
    const float* c1b        = (const float*)d_in[9];
    const float* c2w        = (const float*)d_in[10];
    const float* c2b        = (const float*)d_in[11];
    const float* fxw        = (const float*)d_in[12];
    const float* fxb        = (const float*)d_in[13];
    const float* gcnw       = (const float*)d_in[14];
    const float* gcnb       = (const float*)d_in[15];
    const float* bnm        = (const float*)d_in[16];
    const float* bnv        = (const float*)d_in[17];
    const float* bnw        = (const float*)d_in[18];
    const float* bnb        = (const float*)d_in[19];
    const float* gwl        = (const float*)d_in[20];
    const float* gwr        = (const float*)d_in[21];
    const float* gatt       = (const float*)d_in[22];
    const float* gb         = (const float*)d_in[23];
    const float* f1w        = (const float*)d_in[24];
    const float* f1b        = (const float*)d_in[25];
    const float* f2w        = (const float*)d_in[26];
    const float* f2b        = (const float*)d_in[27];
    float* out = (float*)d_out;

    // Resources created on the (non-capturing) correctness call; reused during capture.
    static cudaStream_t sR = nullptr;
    static cudaEvent_t evF = nullptr, evJ = nullptr;
    static float* p_acc1 = nullptr;
    static float* p_acc2 = nullptr;
    if (!sR) {
        cudaStreamCreateWithFlags(&sR, cudaStreamNonBlocking);
        cudaEventCreateWithFlags(&evF, cudaEventDisableTiming);
        cudaEventCreateWithFlags(&evJ, cudaEventDisableTiming);
        cudaGetSymbolAddress((void**)&p_acc1, g_acc1);
        cudaGetSymbolAddress((void**)&p_acc2, g_acc2);
    }

    // ---- fork: RNA branch on side stream ----
    cudaEventRecord(evF, 0);
    cudaStreamWaitEvent(sR, evF, 0);

    cudaMemsetAsync(p_acc1, 0, NB * 5 * 256 * sizeof(float), sR);
    cudaMemsetAsync(p_acc2, 0, NB * 65 * 256 * sizeof(float), sR);
    k_transpose<<<3000, 256, 0, sR>>>(c1w, 3000, 0);
    k_transpose<<<2998, 256, 0, sR>>>(c2w, 2998, 1);
    k_acc5<<<dim3(64, 12), 256, 0, sR>>>(global_rna);
    k_acc65<<<dim3(64, 2, 4), 128, 0, sR>>>(local_rna);
    k_conv<<<dim3(64, 32), 128, (5 * 128 + 5 * 8) * 4, sR>>>(emb1, c1b, 5, 0);
    k_conv<<<dim3(64, 32), 128, (65 * 128 + 65 * 8) * 4, sR>>>(emb2, c2b, 65, 1);
    k_fc_rna<<<64, 256, 0, sR>>>(fxw, fxb, out);
    cudaEventRecord(evJ, sR);

    // ---- protein branch on main stream ----
    k_init<<<196, 256>>>();
    k_gcn_h<<<6250, dim3(36, 8)>>>(pro_x, gcnw);
    k_edge_count<<<3125, 256>>>(ei, pw);
    k_dinv<<<196, 256>>>();
    k_scanA<<<SCAN_NBLK, 512>>>();
    k_scanB<<<1, 128>>>();
    k_scanC<<<196, 256>>>();
    k_scatter<<<3125, 256>>>(ei, pw);
    k_selfloop<<<196, 256>>>();
    k_gcn_agg<<<6250, 256>>>(gcnb, bnm, bnv, bnw, bnb);
    k_gat_lr<<<(NN + LR_NPB - 1) / LR_NPB, 264>>>(gwl, gwr);
    k_gat<<<6250, 256>>>(gatt, gb);
    k_pool<<<64, 132>>>(pb);
    k_fc1<<<64, 256>>>(f1w, f1b);
    k_fc2<<<64, 256>>>(f2w, f2b, out);

    // ---- join ----
    cudaStreamWaitEvent(0, evJ, 0);
}

// round 6
// speedup vs baseline: 1.6035x; 1.0869x over previous
#include <cuda_runtime.h>
#include <math.h>

#define NN 50000
#define NE 800000
#define E2 850000
#define NB 64
#define SCAN_NBLK 98   // ceil(50000/512)

// ---------------- scratch ----------------
__device__ float g_deg[NN];
__device__ float g_dinv[NN];
__device__ int   g_indeg[NN];
__device__ int   g_off[NN + 1];
__device__ int   g_bsum[128];
__device__ int   g_cur[NN];
__device__ int   g_ssrc[E2];
__device__ float g_snorm[E2];
__device__ float g_h32[NN * 32];    // GCN-transformed, channels 0-31 (128B aligned rows)
__device__ float g_h1[NN];          // channel 32
__device__ float g_xpn[NN * 36];
__device__ float g_xl[NN * 132];
__device__ float g_xr[NN * 132];
__device__ float g_xp2[NN * 132];
__device__ float g_pool[NB * 132];
__device__ float g_cnt[NB];
__device__ float g_W1t[3000 * 256];
__device__ float g_W2t[2998 * 256];
__device__ float g_acc1[NB * 5 * 256];
__device__ float g_acc2[NB * 65 * 256];
__device__ int   g_pos2[NB * 2998];
__device__ int   g_poff2[NB * 66];
__device__ float g_y1[NB * 3872];
__device__ float g_y2[NB * 3872];
__device__ float g_hid[NB * 1024];

// ---------------- init (protein) ----------------
__global__ void k_init() {
    int i = blockIdx.x * blockDim.x + threadIdx.x;
    if (i < NN) { g_deg[i] = 1.0f; g_indeg[i] = 1; }
    if (i < NB * 132) g_pool[i] = 0.0f;
    if (i < NB) g_cnt[i] = 0.0f;
}

__global__ void k_edge_count(const int* __restrict__ ei, const float* __restrict__ w) {
    int e = blockIdx.x * blockDim.x + threadIdx.x;
    if (e >= NE) return;
    int d = ei[NE + e];
    atomicAdd(&g_deg[d], w[e]);
    atomicAdd(&g_indeg[d], 1);
}

__global__ void k_dinv() {
    int i = blockIdx.x * blockDim.x + threadIdx.x;
    if (i < NN) g_dinv[i] = rsqrtf(g_deg[i]);
}

// ---------------- multi-block scan ----------------
__global__ void k_scanA() {
    __shared__ int wsum[16];
    int i = blockIdx.x * 512 + threadIdx.x;
    int lane = threadIdx.x & 31, wid = threadIdx.x >> 5;
    int v = (i < NN) ? g_indeg[i] : 0;
    int x = v;
    #pragma unroll
    for (int off = 1; off < 32; off <<= 1) {
        int t = __shfl_up_sync(0xffffffffu, x, off);
        if (lane >= off) x += t;
    }
    if (lane == 31) wsum[wid] = x;
    __syncthreads();
    if (wid == 0) {
        int s = (lane < 16) ? wsum[lane] : 0;
        #pragma unroll
        for (int off = 1; off < 32; off <<= 1) {
            int t = __shfl_up_sync(0xffffffffu, s, off);
            if (lane >= off) s += t;
        }
        if (lane < 16) wsum[lane] = s;
    }
    __syncthreads();
    int pre = (wid > 0) ? wsum[wid - 1] : 0;
    int incl = x + pre;
    if (i < NN) g_off[i] = incl - v;
    if (threadIdx.x == 511) g_bsum[blockIdx.x] = incl;
}

__global__ void k_scanB() {
    __shared__ int wtot[4];
    int t = threadIdx.x;
    int lane = t & 31, wid = t >> 5;
    int v = (t < SCAN_NBLK) ? g_bsum[t] : 0;
    int x = v;
    #pragma unroll
    for (int off = 1; off < 32; off <<= 1) {
        int tt = __shfl_up_sync(0xffffffffu, x, off);
        if (lane >= off) x += tt;
    }
    if (lane == 31) wtot[wid] = x;
    __syncthreads();
    if (t == 0) {
        int run = 0;
        for (int k = 0; k < 4; k++) { int tmp = wtot[k]; wtot[k] = run; run += tmp; }
        g_off[NN] = run;
    }
    __syncthreads();
    int excl = x - v + wtot[wid];
    if (t < SCAN_NBLK) g_bsum[t] = excl;
}

__global__ void k_scanC() {
    int i = blockIdx.x * blockDim.x + threadIdx.x;
    if (i >= NN) return;
    int val = g_off[i] + g_bsum[i >> 9];
    g_off[i] = val;
    g_cur[i] = val;
}

// ---------------- counting-sort scatter ----------------
__global__ void k_scatter(const int* __restrict__ ei, const float* __restrict__ w) {
    int e = blockIdx.x * blockDim.x + threadIdx.x;
    if (e >= NE) return;
    int s = ei[e], d = ei[NE + e];
    int p = atomicAdd(&g_cur[d], 1);
    g_ssrc[p] = s;
    g_snorm[p] = g_dinv[s] * w[e] * g_dinv[d];
}

__global__ void k_selfloop() {
    int i = blockIdx.x * blockDim.x + threadIdx.x;
    if (i >= NN) return;
    int p = atomicAdd(&g_cur[i], 1);
    g_ssrc[p] = i;
    g_snorm[p] = g_dinv[i] * g_dinv[i];
}

// ---------------- GCN transform ----------------
__global__ void k_gcn_h(const float* __restrict__ x, const float* __restrict__ W) {
    __shared__ float Ws[33 * 33];
    __shared__ float xs[8][33];
    int tx = threadIdx.x, ty = threadIdx.y;
    int tid = ty * 36 + tx;
    for (int i = tid; i < 1089; i += 288) Ws[i] = W[i];
    int n = blockIdx.x * 8 + ty;
    if (n < NN && tx < 33) xs[ty][tx] = x[n * 33 + tx];
    __syncthreads();
    if (n >= NN) return;
    if (tx >= 33) return;
    float a = 0.0f;
    #pragma unroll
    for (int k = 0; k < 33; k++) a += xs[ty][k] * Ws[tx * 33 + k];
    if (tx < 32) g_h32[n * 32 + tx] = a;
    else         g_h1[n] = a;
}

// ---------------- GCN aggregation + relu + BN ----------------
__global__ void k_gcn_agg(const float* __restrict__ gcnb, const float* __restrict__ bm,
                          const float* __restrict__ bv, const float* __restrict__ bw,
                          const float* __restrict__ bb) {
    int d = blockIdx.x * 8 + (threadIdx.x >> 5);
    int lane = threadIdx.x & 31;
    if (d >= NN) return;
    int beg = g_off[d], end = g_off[d + 1];
    float a0 = 0.0f, a1 = 0.0f, b0 = 0.0f, b1 = 0.0f;
    int e = beg;
    for (; e + 2 <= end; e += 2) {
        int sA = g_ssrc[e], sB = g_ssrc[e + 1];
        float nA = g_snorm[e], nB = g_snorm[e + 1];
        a0 += g_h32[sA * 32 + lane] * nA;
        b0 += g_h32[sB * 32 + lane] * nB;
        a1 += g_h1[sA] * nA;
        b1 += g_h1[sB] * nB;
    }
    if (e < end) {
        int sA = g_ssrc[e];
        float nA = g_snorm[e];
        a0 += g_h32[sA * 32 + lane] * nA;
        a1 += g_h1[sA] * nA;
    }
    a0 += b0; a1 += b1;
    float c0 = fmaxf(a0 + gcnb[lane], 0.0f);
    float inv0 = bw[lane] * rsqrtf(bv[lane] + 1e-5f);
    g_xpn[d * 36 + lane] = c0 * inv0 + (bb[lane] - bm[lane] * inv0);
    if (lane == 0) {
        float c1 = fmaxf(a1 + gcnb[32], 0.0f);
        float inv1 = bw[32] * rsqrtf(bv[32] + 1e-5f);
        g_xpn[d * 36 + 32] = c1 * inv1 + (bb[32] - bm[32] * inv1);
        g_xpn[d * 36 + 33] = 0.0f;
        g_xpn[d * 36 + 34] = 0.0f;
        g_xpn[d * 36 + 35] = 0.0f;
    }
}

// ---------------- GAT projections ----------------
#define LR_NPB 64
__global__ void k_gat_lr(const float* __restrict__ wl, const float* __restrict__ wr) {
    __shared__ float Wsh[2 * 132 * 33];
    __shared__ float xs[8][33];
    int t = threadIdx.x;  // 0..263
    for (int i = t; i < 4356; i += 264) Wsh[i] = wl[i];
    for (int i = t; i < 4356; i += 264) Wsh[4356 + i] = wr[i];
    __syncthreads();
    int c = t % 132, side = t / 132;
    float wreg[33];
    #pragma unroll
    for (int k = 0; k < 33; k++) wreg[k] = Wsh[side * 4356 + c * 33 + k];
    float* outb = side ? g_xr : g_xl;
    int n0 = blockIdx.x * LR_NPB;
    int n1 = min(n0 + LR_NPB, NN);
    for (int nb = n0; nb < n1; nb += 8) {
        __syncthreads();
        {
            int u = t / 33, k = t % 33;
            int n = nb + u;
            xs[u][k] = (n < NN) ? g_xpn[n * 36 + k] : 0.0f;
        }
        __syncthreads();
        #pragma unroll
        for (int u = 0; u < 8; u++) {
            int n = nb + u;
            if (n < n1) {
                float a = 0.0f;
                #pragma unroll
                for (int k = 0; k < 33; k++) a += wreg[k] * xs[u][k];
                outb[n * 132 + c] = a;
            }
        }
    }
}

// ---------------- GATv2: online softmax, 2 dsts per warp ----------------
__global__ void k_gat(const float* __restrict__ att, const float* __restrict__ gb) {
    int lane = threadIdx.x & 31, wid = threadIdx.x >> 5;
    int dbase = blockIdx.x * 16;
    const float4* att4 = (const float4*)att;
    const float4* gb4 = (const float4*)gb;
    float4 z = make_float4(0.f, 0.f, 0.f, 0.f);
    float4 at0 = att4[lane];
    float4 at1 = (lane == 0) ? att4[32] : z;
    int cb = 4 * lane;
    bool hA = cb + 0 < 66, hB = cb + 1 < 66, hC = cb + 2 < 66, hD = cb + 3 < 66;

    int dd[2];
    dd[0] = dbase + wid;
    dd[1] = dbase + 8 + wid;
    float4 xr0[2], xr1[2], acc0[2], acc1[2];
    float m0[2], m1[2], s0[2], s1[2];
    int beg[2], len[2];
    int maxlen = 0;
    #pragma unroll
    for (int k = 0; k < 2; k++) {
        int d = dd[k];
        bool ok = d < NN;
        const float4* xr4 = (const float4*)(g_xr + (size_t)(ok ? d : 0) * 132);
        xr0[k] = ok ? xr4[lane] : z;
        xr1[k] = (ok && lane == 0) ? xr4[32] : z;
        acc0[k] = z; acc1[k] = z;
        m0[k] = -1e30f; m1[k] = -1e30f; s0[k] = 0.f; s1[k] = 0.f;
        beg[k] = ok ? g_off[d] : 0;
        int e1 = ok ? g_off[d + 1] : 0;
        len[k] = e1 - beg[k];
        maxlen = max(maxlen, len[k]);
    }
    for (int i = 0; i < maxlen; i++) {
        #pragma unroll
        for (int k = 0; k < 2; k++) {
            if (i >= len[k]) continue;   // warp-uniform branch
            int e = beg[k] + i;
            int s = g_ssrc[e];
            const float4* xl4 = (const float4*)(g_xl + (size_t)s * 132);
            float4 a0 = xl4[lane];
            float4 a1 = (lane == 0) ? xl4[32] : z;
            float p0 = 0.f, p1 = 0.f, v, tt;
            v = a0.x + xr0[k].x; v = v > 0.f ? v : 0.2f * v; tt = v * at0.x; if (hA) p0 += tt; else p1 += tt;
            v = a0.y + xr0[k].y; v = v > 0.f ? v : 0.2f * v; tt = v * at0.y; if (hB) p0 += tt; else p1 += tt;
            v = a0.z + xr0[k].z; v = v > 0.f ? v : 0.2f * v; tt = v * at0.z; if (hC) p0 += tt; else p1 += tt;
            v = a0.w + xr0[k].w; v = v > 0.f ? v : 0.2f * v; tt = v * at0.w; if (hD) p0 += tt; else p1 += tt;
            v = a1.x + xr1[k].x; v = v > 0.f ? v : 0.2f * v; p1 += v * at1.x;
            v = a1.y + xr1[k].y; v = v > 0.f ? v : 0.2f * v; p1 += v * at1.y;
            v = a1.z + xr1[k].z; v = v > 0.f ? v : 0.2f * v; p1 += v * at1.z;
            v = a1.w + xr1[k].w; v = v > 0.f ? v : 0.2f * v; p1 += v * at1.w;
            #pragma unroll
            for (int o = 16; o; o >>= 1) {
                p0 += __shfl_xor_sync(0xffffffffu, p0, o);
                p1 += __shfl_xor_sync(0xffffffffu, p1, o);
            }
            float n0 = fmaxf(m0[k], p0), n1 = fmaxf(m1[k], p1);
            float f0 = __expf(m0[k] - n0), w0 = __expf(p0 - n0);
            float f1 = __expf(m1[k] - n1), w1 = __expf(p1 - n1);
            s0[k] = s0[k] * f0 + w0; m0[k] = n0;
            s1[k] = s1[k] * f1 + w1; m1[k] = n1;
            float F0 = hA ? f0 : f1, W0 = hA ? w0 : w1;
            float F1 = hB ? f0 : f1, W1 = hB ? w0 : w1;
            float F2 = hC ? f0 : f1, W2 = hC ? w0 : w1;
            float F3 = hD ? f0 : f1, W3 = hD ? w0 : w1;
            acc0[k].x = acc0[k].x * F0 + W0 * a0.x;
            acc0[k].y = acc0[k].y * F1 + W1 * a0.y;
            acc0[k].z = acc0[k].z * F2 + W2 * a0.z;
            acc0[k].w = acc0[k].w * F3 + W3 * a0.w;
            acc1[k].x = acc1[k].x * f1 + w1 * a1.x;
            acc1[k].y = acc1[k].y * f1 + w1 * a1.y;
            acc1[k].z = acc1[k].z * f1 + w1 * a1.z;
            acc1[k].w = acc1[k].w * f1 + w1 * a1.w;
        }
    }
    float4 gv = gb4[lane];
    float4 gv1 = (lane == 0) ? gb4[32] : z;
    #pragma unroll
    for (int k = 0; k < 2; k++) {
        int d = dd[k];
        if (d >= NN) continue;
        float4 o;
        o.x = fmaxf(acc0[k].x / (hA ? s0[k] : s1[k]) + gv.x, 0.f);
        o.y = fmaxf(acc0[k].y / (hB ? s0[k] : s1[k]) + gv.y, 0.f);
        o.z = fmaxf(acc0[k].z / (hC ? s0[k] : s1[k]) + gv.z, 0.f);
        o.w = fmaxf(acc0[k].w / (hD ? s0[k] : s1[k]) + gv.w, 0.f);
        ((float4*)(g_xp2 + (size_t)d * 132))[lane] = o;
        if (lane == 0) {
            float4 o1;
            o1.x = fmaxf(acc1[k].x / s1[k] + gv1.x, 0.f);
            o1.y = fmaxf(acc1[k].y / s1[k] + gv1.y, 0.f);
            o1.z = fmaxf(acc1[k].z / s1[k] + gv1.z, 0.f);
            o1.w = fmaxf(acc1[k].w / s1[k] + gv1.w, 0.f);
            ((float4*)(g_xp2 + (size_t)d * 132))[32] = o1;
        }
    }
}

// ---------------- mean pool ----------------
__global__ void k_pool(const int* __restrict__ batch) {
    int c = threadIdx.x;  // 0..131
    int start = blockIdx.x * 782;
    int end = min(start + 782, NN);
    if (start >= end) return;
    int cur = batch[start];
    float sum = 0.0f, cnt = 0.0f;
    for (int n = start; n < end; n++) {
        int g = batch[n];
        if (g != cur) {
            atomicAdd(&g_pool[cur * 132 + c], sum);
            if (c == 0) atomicAdd(&g_cnt[cur], cnt);
            sum = 0.0f; cnt = 0.0f; cur = g;
        }
        sum += g_xp2[n * 132 + c];
        cnt += 1.0f;
    }
    atomicAdd(&g_pool[cur * 132 + c], sum);
    if (c == 0) atomicAdd(&g_cnt[cur], cnt);
}

// ---------------- protein MLP head ----------------
__global__ void k_fc1(const float* __restrict__ w, const float* __restrict__ b) {
    int g = blockIdx.x;
    int obase = blockIdx.y * 256;
    __shared__ float m[132];
    if (threadIdx.x < 132) {
        float cnt = fmaxf(g_cnt[g], 1.0f);
        m[threadIdx.x] = g_pool[g * 132 + threadIdx.x] / cnt;
    }
    __syncthreads();
    int wid = threadIdx.x >> 5, lane = threadIdx.x & 31;
    for (int o = obase + wid; o < obase + 256; o += 8) {
        float acc = 0.0f;
        for (int k = lane; k < 132; k += 32) acc += w[o * 132 + k] * m[k];
        #pragma unroll
        for (int off = 16; off; off >>= 1) acc += __shfl_xor_sync(0xffffffffu, acc, off);
        if (lane == 0) g_hid[g * 1024 + o] = fmaxf(acc + b[o], 0.0f);
    }
}

__global__ void k_fc2(const float* __restrict__ w, const float* __restrict__ b, float* __restrict__ out) {
    int g = blockIdx.x;
    int obase = blockIdx.y * 64;
    int wid = threadIdx.x >> 5, lane = threadIdx.x & 31;
    for (int o = obase + wid; o < obase + 64; o += 8) {
        float acc = 0.0f;
        for (int k = lane; k < 1024; k += 32) acc += w[o * 1024 + k] * g_hid[g * 1024 + k];
        #pragma unroll
        for (int off = 16; off; off >>= 1) acc += __shfl_xor_sync(0xffffffffu, acc, off);
        if (lane == 0) out[8192 + g * 128 + o] = acc + b[o];
    }
}

// ---------------- RNA branch ----------------
__global__ void k_transpose(const float* __restrict__ w, int C, int which) {
    float* wt = which ? g_W2t : g_W1t;
    int t = blockIdx.x * blockDim.x + threadIdx.x;
    if (t >= C * 256) return;
    int c = t >> 8, j = t & 255, o = j >> 3, k = j & 7;
    wt[t] = w[o * C * 8 + c * 8 + k];
}

// V=5: register accumulators, chunked over positions
__global__ void k_acc5(const int* __restrict__ rna) {
    int b = blockIdx.x;
    int c0 = blockIdx.y * 250;
    int j = threadIdx.x;  // 0..255
    const int* row = rna + b * 3000 + c0;
    const float* wt = g_W1t + (size_t)c0 * 256 + j;
    float a[5] = {0.f, 0.f, 0.f, 0.f, 0.f};
    #pragma unroll 10
    for (int c = 0; c < 250; c++) {
        int v = __ldg(&row[c]);
        float w = wt[c * 256];
        #pragma unroll
        for (int u = 0; u < 5; u++) a[u] += (v == u) ? w : 0.0f;
    }
    #pragma unroll
    for (int u = 0; u < 5; u++)
        atomicAdd(&g_acc1[b * 1280 + u * 256 + j], a[u]);
}

// V=65: bucket-sort positions by token per batch
__global__ void k_hist65(const int* __restrict__ rna) {
    __shared__ int cnt[66];
    __shared__ int cur[65];
    int b = blockIdx.x, t = threadIdx.x;  // 128 threads
    if (t < 66) cnt[t] = 0;
    __syncthreads();
    const int* row = rna + b * 2998;
    for (int c = t; c < 2998; c += 128) atomicAdd(&cnt[row[c] + 1], 1);
    __syncthreads();
    if (t == 0) {
        int run = 0;
        for (int v = 0; v < 66; v++) { run += cnt[v]; cnt[v] = run; }
        // cnt[v] now = exclusive offset of bin v (since cnt was shifted by +1)
    }
    __syncthreads();
    if (t < 66) g_poff2[b * 66 + t] = cnt[t];
    if (t < 65) cur[t] = cnt[t];
    __syncthreads();
    for (int c = t; c < 2998; c += 128) {
        int v = row[c];
        int p = atomicAdd(&cur[v], 1);
        g_pos2[b * 2998 + p] = c;
    }
}

// V=65: register accumulation over sorted bins (no atomics, no smem)
__global__ void k_acc65b() {
    int b = blockIdx.x;
    int joff = blockIdx.y * 128;
    int j = threadIdx.x;      // 0..127
    int v0 = blockIdx.z * 17;
    int v1 = min(v0 + 17, 65);
    const float* wt = g_W2t + joff + j;
    const int* pos = g_pos2 + b * 2998;
    const int* poff = g_poff2 + b * 66;
    for (int v = v0; v < v1; v++) {
        int p0 = poff[v], p1 = poff[v + 1];
        float a0 = 0.f, a1 = 0.f, a2 = 0.f, a3 = 0.f;
        int p = p0;
        for (; p + 4 <= p1; p += 4) {
            int c0 = pos[p], c1 = pos[p + 1], c2 = pos[p + 2], c3 = pos[p + 3];
            a0 += wt[(size_t)c0 * 256];
            a1 += wt[(size_t)c1 * 256];
            a2 += wt[(size_t)c2 * 256];
            a3 += wt[(size_t)c3 * 256];
        }
        for (; p < p1; p++) a0 += wt[(size_t)pos[p] * 256];
        g_acc2[b * 16640 + v * 256 + joff + j] = (a0 + a1) + (a2 + a3);
    }
}

__global__ void k_conv(const float* __restrict__ emb, const float* __restrict__ bias, int V, int which) {
    extern __shared__ float sh[];
    const float* acc = which ? g_acc2 : g_acc1;
    float* y = which ? g_y2 : g_y1;
    float* emb_sh = sh;
    float* acc_sh = sh + V * 128;
    int b = blockIdx.x, o = blockIdx.y, t = threadIdx.x;
    for (int i = t; i < V * 128; i += 128) emb_sh[i] = emb[i];
    for (int i = t; i < V * 8; i += 128) {
        int v = i >> 3, k = i & 7;
        acc_sh[i] = acc[b * V * 256 + v * 256 + o * 8 + k];
    }
    __syncthreads();
    if (t < 121) {
        float s = bias[o];
        for (int v = 0; v < V; v++) {
            #pragma unroll
            for (int k = 0; k < 8; k++) s += acc_sh[v * 8 + k] * emb_sh[v * 128 + t + k];
        }
        y[b * 3872 + o * 121 + t] = s;
    }
}

__global__ void k_fc_rna(const float* __restrict__ w, const float* __restrict__ bias, float* __restrict__ out) {
    __shared__ float ys[3872];
    int b = blockIdx.x;
    int obase = blockIdx.y * 32;
    for (int i = threadIdx.x; i < 3872; i += 256)
        ys[i] = 0.5f * (g_y1[b * 3872 + i] + g_y2[b * 3872 + i]);
    __syncthreads();
    int wid = threadIdx.x >> 5, lane = threadIdx.x & 31;
    for (int dcol = obase + wid; dcol < obase + 32; dcol += 8) {
        float acc = 0.0f;
        for (int i = lane; i < 3872; i += 32) acc += w[dcol * 3872 + i] * ys[i];
        #pragma unroll
        for (int off = 16; off; off >>= 1) acc += __shfl_xor_sync(0xffffffffu, acc, off);
        if (lane == 0) out[b * 128 + dcol] = acc + bias[dcol];
    }
}

// ---------------- launch ----------------
extern "C" void kernel_launch(void* const* d_in, const int* in_sizes, int n_in,
                              void* d_out, int out_size) {
    const int*   global_rna = (const int*)d_in[0];
    const int*   local_rna  = (const int*)d_in[1];
    const float* pro_x      = (const float*)d_in[2];
    const int*   ei         = (const int*)d_in[3];
    const float* pw         = (const float*)d_in[4];
    const int*   pb         = (const int*)d_in[5];
    const float* emb1       = (const float*)d_in[6];
    const float* emb2       = (const float*)d_in[7];
    const float* c1w        = (const float*)d_in[8];
    const float* c1b        = (const float*)d_in[9];
    const float* c2w        = (const float*)d_in[10];
    const float* c2b        = (const float*)d_in[11];
    const float* fxw        = (const float*)d_in[12];
    const float* fxb        = (const float*)d_in[13];
    const float* gcnw       = (const float*)d_in[14];
    const float* gcnb       = (const float*)d_in[15];
    const float* bnm        = (const float*)d_in[16];
    const float* bnv        = (const float*)d_in[17];
    const float* bnw        = (const float*)d_in[18];
    const float* bnb        = (const float*)d_in[19];
    const float* gwl        = (const float*)d_in[20];
    const float* gwr        = (const float*)d_in[21];
    const float* gatt       = (const float*)d_in[22];
    const float* gb         = (const float*)d_in[23];
    const float* f1w        = (const float*)d_in[24];
    const float* f1b        = (const float*)d_in[25];
    const float* f2w        = (const float*)d_in[26];
    const float* f2b        = (const float*)d_in[27];
    float* out = (float*)d_out;

    static cudaStream_t sR = nullptr;
    static cudaEvent_t evF = nullptr, evJ = nullptr;
    static float* p_acc1 = nullptr;
    if (!sR) {
        cudaStreamCreateWithFlags(&sR, cudaStreamNonBlocking);
        cudaEventCreateWithFlags(&evF, cudaEventDisableTiming);
        cudaEventCreateWithFlags(&evJ, cudaEventDisableTiming);
        cudaGetSymbolAddress((void**)&p_acc1, g_acc1);
    }

    // ---- fork: RNA branch on side stream ----
    cudaEventRecord(evF, 0);
    cudaStreamWaitEvent(sR, evF, 0);

    cudaMemsetAsync(p_acc1, 0, NB * 5 * 256 * sizeof(float), sR);
    k_transpose<<<3000, 256, 0, sR>>>(c1w, 3000, 0);
    k_transpose<<<2998, 256, 0, sR>>>(c2w, 2998, 1);
    k_hist65<<<64, 128, 0, sR>>>(local_rna);
    k_acc5<<<dim3(64, 12), 256, 0, sR>>>(global_rna);
    k_acc65b<<<dim3(64, 2, 4), 128, 0, sR>>>();
    k_conv<<<dim3(64, 32), 128, (5 * 128 + 5 * 8) * 4, sR>>>(emb1, c1b, 5, 0);
    k_conv<<<dim3(64, 32), 128, (65 * 128 + 65 * 8) * 4, sR>>>(emb2, c2b, 65, 1);
    k_fc_rna<<<dim3(64, 4), 256, 0, sR>>>(fxw, fxb, out);
    cudaEventRecord(evJ, sR);

    // ---- protein branch on main stream ----
    k_init<<<196, 256>>>();
    k_gcn_h<<<6250, dim3(36, 8)>>>(pro_x, gcnw);
    k_edge_count<<<3125, 256>>>(ei, pw);
    k_dinv<<<196, 256>>>();
    k_scanA<<<SCAN_NBLK, 512>>>();
    k_scanB<<<1, 128>>>();
    k_scanC<<<196, 256>>>();
    k_scatter<<<3125, 256>>>(ei, pw);
    k_selfloop<<<196, 256>>>();
    k_gcn_agg<<<6250, 256>>>(gcnb, bnm, bnv, bnw, bnb);
    k_gat_lr<<<(NN + LR_NPB - 1) / LR_NPB, 264>>>(gwl, gwr);
    k_gat<<<3125, 256>>>(gatt, gb);
    k_pool<<<64, 132>>>(pb);
    k_fc1<<<dim3(64, 4), 256>>>(f1w, f1b);
    k_fc2<<<dim3(64, 2), 256>>>(f2w, f2b, out);

    // ---- join ----
    cudaStreamWaitEvent(0, evJ, 0);
}